// round 5
// baseline (speedup 1.0000x reference)
#include <cuda_runtime.h>
#include <cstdint>

// ConditionalODE: fused MLP forward + exact 2-tangent JVP divergence.
// B=2048, S=64, D=2, C=128, HIDDEN=512x3. 131072 tokens.
// Per CTA: 16 tokens; state rows [0..15]=primal h, [16..31]=u0, [32..47]=u1.
// Layers 1,2: GEMM [48x512]x[512x512] (weights rows 2..513), te/pos folded
// into per-token bias. Layer 0: primal GEMM K=130; tangents = W0 rows 2,3.
// LN+softplus JVP fused elementwise (warp per token). Layer 3: warp dots.

#define NTOK 131072
#define EPS  1e-5f

__device__ __forceinline__ void cp_async16(float* s, const float* g) {
    unsigned u = (unsigned)__cvta_generic_to_shared(s);
    asm volatile("cp.async.cg.shared.global [%0], [%1], 16;\n" :: "r"(u), "l"(g) : "memory");
}
__device__ __forceinline__ void cp_commit() {
    asm volatile("cp.async.commit_group;\n" ::: "memory");
}
__device__ __forceinline__ void cp_wait0() {
    asm volatile("cp.async.wait_group 0;\n" ::: "memory");
}
__device__ __forceinline__ void cp_wait1() {
    asm volatile("cp.async.wait_group 1;\n" ::: "memory");
}

// GEMM: sOut[r][n] = sum_k sIn[r][k] * Wb[k][n], rows = RPT*16, N=512, K runtime.
// Wb row-major with row stride 512 floats. W k-panels (8x512) staged to smem
// via cp.async double buffer. 512 threads: ty=warp (16), tx=lane (32).
// Thread computes RPT rows x 16 cols (4 groups of float4 spread across N).
template<int RPT>
__device__ __forceinline__ void gemm_tile(
    const float* __restrict__ Wb, int K,
    const float* __restrict__ sIn, float* __restrict__ sW, float* __restrict__ sOut)
{
    const int tid = threadIdx.x;
    const int ty = tid >> 5, tx = tid & 31;
    const int rowBase = ty * RPT;
    float acc[RPT][16];
#pragma unroll
    for (int j = 0; j < RPT; ++j)
#pragma unroll
        for (int m = 0; m < 16; ++m) acc[j][m] = 0.f;

    const int NP = K >> 3;          // number of 8-row weight panels
    const int K4 = NP << 3;
    const int skk  = tid >> 6;      // 0..7   panel row
    const int scol = (tid & 63) * 8;// 8 floats per thread

    if (NP > 0) {
        cp_async16(sW + skk*512 + scol,     Wb + skk*512 + scol);
        cp_async16(sW + skk*512 + scol + 4, Wb + skk*512 + scol + 4);
        cp_commit();
    }
    for (int p = 0; p < NP; ++p) {
        float* cb = sW + (p & 1) * 4096;
        if (p + 1 < NP) {
            float* nb = sW + ((p + 1) & 1) * 4096;
            const float* src = Wb + (p + 1) * 4096;
            cp_async16(nb + skk*512 + scol,     src + skk*512 + scol);
            cp_async16(nb + skk*512 + scol + 4, src + skk*512 + scol + 4);
            cp_commit();
            cp_wait1();
        } else {
            cp_wait0();
        }
        __syncthreads();
#pragma unroll
        for (int kk4 = 0; kk4 < 8; kk4 += 4) {
            const int kglob = (p << 3) + kk4;
            float4 a[RPT];
#pragma unroll
            for (int j = 0; j < RPT; ++j)
                a[j] = *(const float4*)&sIn[(rowBase + j)*512 + kglob];
#pragma unroll
            for (int gs = 0; gs < 4; ++gs) {
                const int c = gs*128 + tx*4;
                float4 b0 = *(const float4*)&cb[(kk4+0)*512 + c];
                float4 b1 = *(const float4*)&cb[(kk4+1)*512 + c];
                float4 b2 = *(const float4*)&cb[(kk4+2)*512 + c];
                float4 b3 = *(const float4*)&cb[(kk4+3)*512 + c];
#pragma unroll
                for (int j = 0; j < RPT; ++j) {
                    float4 av = a[j];
                    float* ac = &acc[j][gs*4];
                    ac[0] = fmaf(av.x, b0.x, ac[0]); ac[0] = fmaf(av.y, b1.x, ac[0]);
                    ac[0] = fmaf(av.z, b2.x, ac[0]); ac[0] = fmaf(av.w, b3.x, ac[0]);
                    ac[1] = fmaf(av.x, b0.y, ac[1]); ac[1] = fmaf(av.y, b1.y, ac[1]);
                    ac[1] = fmaf(av.z, b2.y, ac[1]); ac[1] = fmaf(av.w, b3.y, ac[1]);
                    ac[2] = fmaf(av.x, b0.z, ac[2]); ac[2] = fmaf(av.y, b1.z, ac[2]);
                    ac[2] = fmaf(av.z, b2.z, ac[2]); ac[2] = fmaf(av.w, b3.z, ac[2]);
                    ac[3] = fmaf(av.x, b0.w, ac[3]); ac[3] = fmaf(av.y, b1.w, ac[3]);
                    ac[3] = fmaf(av.z, b2.w, ac[3]); ac[3] = fmaf(av.w, b3.w, ac[3]);
                }
            }
        }
        __syncthreads();
    }
    // K remainder (layer 0: k = 128,129)
    for (int k = K4; k < K; ++k) {
#pragma unroll
        for (int gs = 0; gs < 4; ++gs) {
            const int c = gs*128 + tx*4;
            float4 bv = *(const float4*)&Wb[k*512 + c];
#pragma unroll
            for (int j = 0; j < RPT; ++j) {
                float av = sIn[(rowBase + j)*512 + k];
                acc[j][gs*4+0] = fmaf(av, bv.x, acc[j][gs*4+0]);
                acc[j][gs*4+1] = fmaf(av, bv.y, acc[j][gs*4+1]);
                acc[j][gs*4+2] = fmaf(av, bv.z, acc[j][gs*4+2]);
                acc[j][gs*4+3] = fmaf(av, bv.w, acc[j][gs*4+3]);
            }
        }
    }
#pragma unroll
    for (int j = 0; j < RPT; ++j)
#pragma unroll
        for (int gs = 0; gs < 4; ++gs) {
            float4 v = make_float4(acc[j][gs*4+0], acc[j][gs*4+1],
                                   acc[j][gs*4+2], acc[j][gs*4+3]);
            *(float4*)&sOut[(rowBase + j)*512 + gs*128 + tx*4] = v;
        }
}

// Fused bias(te/pos) + LayerNorm + softplus, with JVP for two tangents.
// One warp per token (16 warps). In-place on buf.
__device__ __forceinline__ void elementwise_ln(
    float* __restrict__ buf,
    const float* __restrict__ bvec, const float* __restrict__ gvec,
    const float* __restrict__ bevec, const float* __restrict__ Wfull,
    float tval, int tok0)
{
    const int i = threadIdx.x >> 5;
    const int l = threadIdx.x & 31;
    const float pos = (float)(((tok0 + i) & 63) + 1) * (1.f/64.f);
    float* xr  = buf + i*512;
    float* u0r = buf + (16+i)*512;
    float* u1r = buf + (32+i)*512;

    float s1=0.f,s2=0.f,s3=0.f,s4=0.f,s5=0.f,s6=0.f;
    for (int k = l; k < 512; k += 32) {
        float cv = bvec[k] + tval*Wfull[k] + pos*Wfull[512+k];
        float x = xr[k] + cv;
        xr[k] = x;
        float u0 = u0r[k], u1 = u1r[k];
        s1 += x;     s2 += x*x;
        s3 += u0;    s4 += x*u0;
        s5 += u1;    s6 += x*u1;
    }
#pragma unroll
    for (int o = 16; o > 0; o >>= 1) {
        s1 += __shfl_xor_sync(0xffffffffu, s1, o);
        s2 += __shfl_xor_sync(0xffffffffu, s2, o);
        s3 += __shfl_xor_sync(0xffffffffu, s3, o);
        s4 += __shfl_xor_sync(0xffffffffu, s4, o);
        s5 += __shfl_xor_sync(0xffffffffu, s5, o);
        s6 += __shfl_xor_sync(0xffffffffu, s6, o);
    }
    const float inv = 1.f/512.f;
    float mu   = s1*inv;
    float var  = s2*inv - mu*mu;
    float r    = rsqrtf(var + EPS);
    float mu0  = s3*inv, mu1 = s5*inv;
    float cov0 = s4*inv - mu*mu0;
    float cov1 = s6*inv - mu*mu1;
    float r3c0 = r*r*r*cov0;
    float r3c1 = r*r*r*cov1;
    for (int k = l; k < 512; k += 32) {
        float x  = xr[k];
        float xc = x - mu;
        float gg = gvec[k];
        float y  = fmaf(xc*r, gg, bevec[k]);
        float e  = __expf(-fabsf(y));
        float sp = fmaxf(y, 0.f) + log1pf(e);
        float sg = (y >= 0.f) ? (1.f/(1.f+e)) : (e/(1.f+e));
        float du0 = sg * gg * (r*(u0r[k]-mu0) - xc*r3c0);
        float du1 = sg * gg * (r*(u1r[k]-mu1) - xc*r3c1);
        xr[k]  = sp;
        u0r[k] = du0;
        u1r[k] = du1;
    }
}

__global__ void __launch_bounds__(512, 1) ode_kernel(
    const float* __restrict__ tptr, const float* __restrict__ z,
    const float* __restrict__ cond,
    const float* __restrict__ W0, const float* __restrict__ b0,
    const float* __restrict__ g0, const float* __restrict__ be0,
    const float* __restrict__ W1, const float* __restrict__ b1,
    const float* __restrict__ g1, const float* __restrict__ be1,
    const float* __restrict__ W2, const float* __restrict__ b2,
    const float* __restrict__ g2, const float* __restrict__ be2,
    const float* __restrict__ W3, const float* __restrict__ b3,
    float* __restrict__ out)
{
    extern __shared__ float smem[];
    float* sA = smem;            // 48x512
    float* sB = smem + 24576;    // 48x512
    float* sW = smem + 49152;    // 2 x (8x512) weight panels
    const int tid  = threadIdx.x;
    const int tok0 = blockIdx.x * 16;
    const float tval = tptr[0];

    // Layer-0 features into sA rows 0..15, cols 0..129: [z0,z1,cond0..127]
    for (int idx = tid; idx < 16*130; idx += 512) {
        int i = idx / 130, k = idx - i*130;
        int token = tok0 + i;
        float v = (k < 2) ? z[token*2 + k] : cond[(token >> 6)*128 + (k - 2)];
        sA[i*512 + k] = v;
    }
    __syncthreads();

    // Layer 0: primal GEMM (weights rows 2..131), tangents = W0 rows 2,3
    gemm_tile<1>(W0 + 1024, 130, sA, sW, sB);
    {
        int n = tid;  // 512 threads cover n in [0,512)
        float v0 = W0[1024 + n];
        float v1 = W0[1536 + n];
#pragma unroll
        for (int i = 0; i < 16; ++i) {
            sB[(16+i)*512 + n] = v0;
            sB[(32+i)*512 + n] = v1;
        }
    }
    __syncthreads();
    elementwise_ln(sB, b0, g0, be0, W0, tval, tok0);
    __syncthreads();

    // Layer 1
    gemm_tile<3>(W1 + 1024, 512, sB, sW, sA);
    __syncthreads();
    elementwise_ln(sA, b1, g1, be1, W1, tval, tok0);
    __syncthreads();

    // Layer 2
    gemm_tile<3>(W2 + 1024, 512, sA, sW, sB);
    __syncthreads();
    elementwise_ln(sB, b2, g2, be2, W2, tval, tok0);
    __syncthreads();

    // Layer 3: per-token dots (warp per token)
    {
        const int i = tid >> 5, l = tid & 31;
        const int token = tok0 + i;
        const float pos = (float)((token & 63) + 1) * (1.f/64.f);
        const float* xr  = sB + i*512;
        const float* u0r = sB + (16+i)*512;
        const float* u1r = sB + (32+i)*512;
        float a0=0.f, a1=0.f, d0=0.f, d1=0.f;
        for (int k = l; k < 512; k += 32) {
            float2 wv = *(const float2*)&W3[(2+k)*2];
            float h = xr[k];
            a0 = fmaf(h, wv.x, a0);
            a1 = fmaf(h, wv.y, a1);
            d0 = fmaf(u0r[k], wv.x, d0);
            d1 = fmaf(u1r[k], wv.y, d1);
        }
#pragma unroll
        for (int o = 16; o > 0; o >>= 1) {
            a0 += __shfl_xor_sync(0xffffffffu, a0, o);
            a1 += __shfl_xor_sync(0xffffffffu, a1, o);
            d0 += __shfl_xor_sync(0xffffffffu, d0, o);
            d1 += __shfl_xor_sync(0xffffffffu, d1, o);
        }
        if (l == 0) {
            out[token*2 + 0] = a0 + b3[0] + tval*W3[0] + pos*W3[2];
            out[token*2 + 1] = a1 + b3[1] + tval*W3[1] + pos*W3[3];
            out[2*NTOK + token] = -(d0 + d1);
        }
    }
}

extern "C" void kernel_launch(void* const* d_in, const int* in_sizes, int n_in,
                              void* d_out, int out_size)
{
    const float* t    = (const float*)d_in[0];
    const float* z    = (const float*)d_in[1];
    const float* cond = (const float*)d_in[2];
    const float* W0   = (const float*)d_in[3];
    const float* b0   = (const float*)d_in[4];
    const float* g0   = (const float*)d_in[5];
    const float* be0  = (const float*)d_in[6];
    const float* W1   = (const float*)d_in[7];
    const float* b1   = (const float*)d_in[8];
    const float* g1   = (const float*)d_in[9];
    const float* be1  = (const float*)d_in[10];
    const float* W2   = (const float*)d_in[11];
    const float* b2   = (const float*)d_in[12];
    const float* g2   = (const float*)d_in[13];
    const float* be2  = (const float*)d_in[14];
    const float* W3   = (const float*)d_in[15];
    const float* b3   = (const float*)d_in[16];
    float* out = (float*)d_out;

    const size_t smem_bytes = 57344 * sizeof(float);  // 229376 B
    cudaFuncSetAttribute(ode_kernel, cudaFuncAttributeMaxDynamicSharedMemorySize,
                         (int)smem_bytes);
    ode_kernel<<<NTOK/16, 512, smem_bytes>>>(
        t, z, cond, W0, b0, g0, be0, W1, b1, g1, be1,
        W2, b2, g2, be2, W3, b3, out);
}

// round 6
// speedup vs baseline: 1.2098x; 1.2098x over previous
#include <cuda_runtime.h>
#include <cstdint>

// ConditionalODE: fused MLP forward + exact 2-tangent JVP divergence.
// Round 6: (a) packed-fp32 GEMM via PTX fma.rn.f32x2 (FFMA2, 2x FFMA rate);
//          (b) layer-0 cond@W0 hoisted per-batch into g_condW (pre-kernel),
//              so the main kernel runs only two K=512 GEMMs.
// Per CTA: 16 tokens; rows [0..15]=primal, [16..31]=u0, [32..47]=u1.

#define NTOK 131072
#define EPS  1e-5f

__device__ float g_condW[2048 * 512];   // per-batch cond @ W0[4:132]  (4 MB)

__device__ __forceinline__ void cp_async16(float* s, const float* g) {
    unsigned u = (unsigned)__cvta_generic_to_shared(s);
    asm volatile("cp.async.cg.shared.global [%0], [%1], 16;\n" :: "r"(u), "l"(g) : "memory");
}
__device__ __forceinline__ void cp_commit() {
    asm volatile("cp.async.commit_group;\n" ::: "memory");
}
__device__ __forceinline__ void cp_wait0() {
    asm volatile("cp.async.wait_group 0;\n" ::: "memory");
}
__device__ __forceinline__ void cp_wait1() {
    asm volatile("cp.async.wait_group 1;\n" ::: "memory");
}

// ---- packed fp32 helpers (sm_103a f32x2 pipe) ----
__device__ __forceinline__ unsigned long long splat2(float a) {
    unsigned long long r;
    unsigned ai = __float_as_uint(a);
    asm("mov.b64 %0, {%1, %1};" : "=l"(r) : "r"(ai));
    return r;
}
__device__ __forceinline__ void ffma2(unsigned long long& d,
                                      unsigned long long a, unsigned long long b) {
    asm("fma.rn.f32x2 %0, %1, %2, %0;" : "+l"(d) : "l"(a), "l"(b));
}

// GEMM: sOut[48][512] = sIn[48][512] @ Wb[512][512] using FFMA2.
// 512 threads: rg = tid>>6 owns rows rg*6..rg*6+5; cg = tid&63 owns columns
// {cg*4..cg*4+3} and {256+cg*4..+3} as four f32x2 pairs. A loads are
// warp-uniform (broadcast); B loads are lane-consecutive float4 (conflict-free).
// Weight k-panels (8x512) staged to smem via cp.async double buffer.
__device__ __forceinline__ void gemm512(
    const float* __restrict__ Wb,
    const float* __restrict__ sIn, float* __restrict__ sW, float* __restrict__ sOut)
{
    const int tid = threadIdx.x;
    const int rg = tid >> 6;
    const int cg = tid & 63;
    const int rowBase = rg * 6;
    const int c0 = cg * 4;

    unsigned long long acc[6][4];
#pragma unroll
    for (int j = 0; j < 6; ++j)
#pragma unroll
        for (int m = 0; m < 4; ++m) acc[j][m] = 0ull;

    const int skk  = tid >> 6;
    const int scol = (tid & 63) * 8;

    cp_async16(sW + skk*512 + scol,     Wb + skk*512 + scol);
    cp_async16(sW + skk*512 + scol + 4, Wb + skk*512 + scol + 4);
    cp_commit();

#pragma unroll 1
    for (int p = 0; p < 64; ++p) {
        float* cb = sW + (p & 1) * 4096;
        if (p + 1 < 64) {
            float* nb = sW + ((p + 1) & 1) * 4096;
            const float* src = Wb + (p + 1) * 4096;
            cp_async16(nb + skk*512 + scol,     src + skk*512 + scol);
            cp_async16(nb + skk*512 + scol + 4, src + skk*512 + scol + 4);
            cp_commit();
            cp_wait1();
        } else {
            cp_wait0();
        }
        __syncthreads();
#pragma unroll
        for (int kk = 0; kk < 8; kk += 4) {
            const int kg = (p << 3) + kk;
            float4 a[6];
#pragma unroll
            for (int j = 0; j < 6; ++j)
                a[j] = *(const float4*)&sIn[(rowBase + j)*512 + kg];
#pragma unroll
            for (int kq = 0; kq < 4; ++kq) {
                ulonglong2 bA = *(const ulonglong2*)&cb[(kk + kq)*512 + c0];
                ulonglong2 bB = *(const ulonglong2*)&cb[(kk + kq)*512 + c0 + 256];
#pragma unroll
                for (int j = 0; j < 6; ++j) {
                    float av = (kq == 0) ? a[j].x : (kq == 1) ? a[j].y
                             : (kq == 2) ? a[j].z : a[j].w;
                    unsigned long long a2 = splat2(av);
                    ffma2(acc[j][0], a2, bA.x);
                    ffma2(acc[j][1], a2, bA.y);
                    ffma2(acc[j][2], a2, bB.x);
                    ffma2(acc[j][3], a2, bB.y);
                }
            }
        }
        __syncthreads();
    }
#pragma unroll
    for (int j = 0; j < 6; ++j) {
        *(ulonglong2*)&sOut[(rowBase + j)*512 + c0]       = make_ulonglong2(acc[j][0], acc[j][1]);
        *(ulonglong2*)&sOut[(rowBase + j)*512 + c0 + 256] = make_ulonglong2(acc[j][2], acc[j][3]);
    }
}

// Fused bias(te/pos) + LayerNorm + softplus, with JVP for two tangents.
// One warp per token (16 warps). In-place on buf.
__device__ __forceinline__ void elementwise_ln(
    float* __restrict__ buf,
    const float* __restrict__ bvec, const float* __restrict__ gvec,
    const float* __restrict__ bevec, const float* __restrict__ Wfull,
    float tval, int tok0)
{
    const int i = threadIdx.x >> 5;
    const int l = threadIdx.x & 31;
    const float pos = (float)(((tok0 + i) & 63) + 1) * (1.f/64.f);
    float* xr  = buf + i*512;
    float* u0r = buf + (16+i)*512;
    float* u1r = buf + (32+i)*512;

    float s1=0.f,s2=0.f,s3=0.f,s4=0.f,s5=0.f,s6=0.f;
    for (int k = l; k < 512; k += 32) {
        float cv = bvec[k] + tval*Wfull[k] + pos*Wfull[512+k];
        float x = xr[k] + cv;
        xr[k] = x;
        float u0 = u0r[k], u1 = u1r[k];
        s1 += x;     s2 += x*x;
        s3 += u0;    s4 += x*u0;
        s5 += u1;    s6 += x*u1;
    }
#pragma unroll
    for (int o = 16; o > 0; o >>= 1) {
        s1 += __shfl_xor_sync(0xffffffffu, s1, o);
        s2 += __shfl_xor_sync(0xffffffffu, s2, o);
        s3 += __shfl_xor_sync(0xffffffffu, s3, o);
        s4 += __shfl_xor_sync(0xffffffffu, s4, o);
        s5 += __shfl_xor_sync(0xffffffffu, s5, o);
        s6 += __shfl_xor_sync(0xffffffffu, s6, o);
    }
    const float inv = 1.f/512.f;
    float mu   = s1*inv;
    float var  = s2*inv - mu*mu;
    float r    = rsqrtf(var + EPS);
    float mu0  = s3*inv, mu1 = s5*inv;
    float cov0 = s4*inv - mu*mu0;
    float cov1 = s6*inv - mu*mu1;
    float r3c0 = r*r*r*cov0;
    float r3c1 = r*r*r*cov1;
    for (int k = l; k < 512; k += 32) {
        float x  = xr[k];
        float xc = x - mu;
        float gg = gvec[k];
        float y  = fmaf(xc*r, gg, bevec[k]);
        float e  = __expf(-fabsf(y));
        float sp = fmaxf(y, 0.f) + log1pf(e);
        float sg = (y >= 0.f) ? (1.f/(1.f+e)) : (e/(1.f+e));
        float du0 = sg * gg * (r*(u0r[k]-mu0) - xc*r3c0);
        float du1 = sg * gg * (r*(u1r[k]-mu1) - xc*r3c1);
        xr[k]  = sp;
        u0r[k] = du0;
        u1r[k] = du1;
    }
}

// Pre-kernel: g_condW[b][n] = sum_c cond[b][c] * W0[(4+c)*512+n].
// 256 CTAs x 512 thr, 8 batches per CTA; W0 column read once per CTA (L2-hot).
__global__ void __launch_bounds__(512) condw_kernel(
    const float* __restrict__ cond, const float* __restrict__ W0)
{
    __shared__ float sc[8 * 128];
    const int n  = threadIdx.x;
    const int bb = blockIdx.x * 8;
    for (int idx = n; idx < 8*128; idx += 512) sc[idx] = cond[bb*128 + idx];
    __syncthreads();
    float acc[8];
#pragma unroll
    for (int j = 0; j < 8; ++j) acc[j] = 0.f;
    for (int c = 0; c < 128; ++c) {
        float w = W0[(4 + c)*512 + n];
#pragma unroll
        for (int j = 0; j < 8; ++j) acc[j] = fmaf(sc[j*128 + c], w, acc[j]);
    }
#pragma unroll
    for (int j = 0; j < 8; ++j) g_condW[(bb + j)*512 + n] = acc[j];
}

__global__ void __launch_bounds__(512, 1) ode_kernel(
    const float* __restrict__ tptr, const float* __restrict__ z,
    const float* __restrict__ cond,
    const float* __restrict__ W0, const float* __restrict__ b0,
    const float* __restrict__ g0, const float* __restrict__ be0,
    const float* __restrict__ W1, const float* __restrict__ b1,
    const float* __restrict__ g1, const float* __restrict__ be1,
    const float* __restrict__ W2, const float* __restrict__ b2,
    const float* __restrict__ g2, const float* __restrict__ be2,
    const float* __restrict__ W3, const float* __restrict__ b3,
    float* __restrict__ out)
{
    extern __shared__ float smem[];
    float* sA = smem;            // 48x512
    float* sB = smem + 24576;    // 48x512
    float* sW = smem + 49152;    // 2 x (8x512) weight panels
    const int tid  = threadIdx.x;
    const int tok0 = blockIdx.x * 16;
    const float tval = tptr[0];

    // ---- Layer 0 (algebraic): primal = z0*W0r2 + z1*W0r3 + condW; u0=W0r2, u1=W0r3
    if (tid < 32) sW[tid] = z[tok0*2 + tid];
    __syncthreads();
    {
        const int n = tid;
        float w2  = W0[1024 + n];
        float w3  = W0[1536 + n];
        float cwv = g_condW[(tok0 >> 6)*512 + n];
#pragma unroll
        for (int i = 0; i < 16; ++i) {
            float z0 = sW[i*2], z1 = sW[i*2 + 1];
            sB[i*512 + n]        = fmaf(z0, w2, fmaf(z1, w3, cwv));
            sB[(16 + i)*512 + n] = w2;
            sB[(32 + i)*512 + n] = w3;
        }
    }
    __syncthreads();
    elementwise_ln(sB, b0, g0, be0, W0, tval, tok0);
    __syncthreads();

    // ---- Layer 1
    gemm512(W1 + 1024, sB, sW, sA);
    __syncthreads();
    elementwise_ln(sA, b1, g1, be1, W1, tval, tok0);
    __syncthreads();

    // ---- Layer 2
    gemm512(W2 + 1024, sA, sW, sB);
    __syncthreads();
    elementwise_ln(sB, b2, g2, be2, W2, tval, tok0);
    __syncthreads();

    // ---- Layer 3: per-token dots (warp per token)
    {
        const int i = tid >> 5, l = tid & 31;
        const int token = tok0 + i;
        const float pos = (float)((token & 63) + 1) * (1.f/64.f);
        const float* xr  = sB + i*512;
        const float* u0r = sB + (16+i)*512;
        const float* u1r = sB + (32+i)*512;
        float a0=0.f, a1=0.f, d0=0.f, d1=0.f;
        for (int k = l; k < 512; k += 32) {
            float2 wv = *(const float2*)&W3[(2+k)*2];
            float h = xr[k];
            a0 = fmaf(h, wv.x, a0);
            a1 = fmaf(h, wv.y, a1);
            d0 = fmaf(u0r[k], wv.x, d0);
            d1 = fmaf(u1r[k], wv.y, d1);
        }
#pragma unroll
        for (int o = 16; o > 0; o >>= 1) {
            a0 += __shfl_xor_sync(0xffffffffu, a0, o);
            a1 += __shfl_xor_sync(0xffffffffu, a1, o);
            d0 += __shfl_xor_sync(0xffffffffu, d0, o);
            d1 += __shfl_xor_sync(0xffffffffu, d1, o);
        }
        if (l == 0) {
            out[token*2 + 0] = a0 + b3[0] + tval*W3[0] + pos*W3[2];
            out[token*2 + 1] = a1 + b3[1] + tval*W3[1] + pos*W3[3];
            out[2*NTOK + token] = -(d0 + d1);
        }
    }
}

extern "C" void kernel_launch(void* const* d_in, const int* in_sizes, int n_in,
                              void* d_out, int out_size)
{
    const float* t    = (const float*)d_in[0];
    const float* z    = (const float*)d_in[1];
    const float* cond = (const float*)d_in[2];
    const float* W0   = (const float*)d_in[3];
    const float* b0   = (const float*)d_in[4];
    const float* g0   = (const float*)d_in[5];
    const float* be0  = (const float*)d_in[6];
    const float* W1   = (const float*)d_in[7];
    const float* b1   = (const float*)d_in[8];
    const float* g1   = (const float*)d_in[9];
    const float* be1  = (const float*)d_in[10];
    const float* W2   = (const float*)d_in[11];
    const float* b2   = (const float*)d_in[12];
    const float* g2   = (const float*)d_in[13];
    const float* be2  = (const float*)d_in[14];
    const float* W3   = (const float*)d_in[15];
    const float* b3   = (const float*)d_in[16];
    float* out = (float*)d_out;

    condw_kernel<<<256, 512>>>(cond, W0);

    const size_t smem_bytes = 57344 * sizeof(float);  // 229376 B
    cudaFuncSetAttribute(ode_kernel, cudaFuncAttributeMaxDynamicSharedMemorySize,
                         (int)smem_bytes);
    ode_kernel<<<NTOK/16, 512, smem_bytes>>>(
        t, z, cond, W0, b0, g0, be0, W1, b1, g1, be1,
        W2, b2, g2, be2, W3, b3, out);
}

// round 10
// speedup vs baseline: 1.2098x; 1.0000x over previous
#include <cuda_runtime.h>
#include <cstdint>

// ConditionalODE: fused MLP forward + exact 2-tangent JVP divergence.
// Round 6: (a) packed-fp32 GEMM via PTX fma.rn.f32x2 (FFMA2, 2x FFMA rate);
//          (b) layer-0 cond@W0 hoisted per-batch into g_condW (pre-kernel),
//              so the main kernel runs only two K=512 GEMMs.
// Per CTA: 16 tokens; rows [0..15]=primal, [16..31]=u0, [32..47]=u1.

#define NTOK 131072
#define EPS  1e-5f

__device__ float g_condW[2048 * 512];   // per-batch cond @ W0[4:132]  (4 MB)

__device__ __forceinline__ void cp_async16(float* s, const float* g) {
    unsigned u = (unsigned)__cvta_generic_to_shared(s);
    asm volatile("cp.async.cg.shared.global [%0], [%1], 16;\n" :: "r"(u), "l"(g) : "memory");
}
__device__ __forceinline__ void cp_commit() {
    asm volatile("cp.async.commit_group;\n" ::: "memory");
}
__device__ __forceinline__ void cp_wait0() {
    asm volatile("cp.async.wait_group 0;\n" ::: "memory");
}
__device__ __forceinline__ void cp_wait1() {
    asm volatile("cp.async.wait_group 1;\n" ::: "memory");
}

// ---- packed fp32 helpers (sm_103a f32x2 pipe) ----
__device__ __forceinline__ unsigned long long splat2(float a) {
    unsigned long long r;
    unsigned ai = __float_as_uint(a);
    asm("mov.b64 %0, {%1, %1};" : "=l"(r) : "r"(ai));
    return r;
}
__device__ __forceinline__ void ffma2(unsigned long long& d,
                                      unsigned long long a, unsigned long long b) {
    asm("fma.rn.f32x2 %0, %1, %2, %0;" : "+l"(d) : "l"(a), "l"(b));
}

// GEMM: sOut[48][512] = sIn[48][512] @ Wb[512][512] using FFMA2.
// 512 threads: rg = tid>>6 owns rows rg*6..rg*6+5; cg = tid&63 owns columns
// {cg*4..cg*4+3} and {256+cg*4..+3} as four f32x2 pairs. A loads are
// warp-uniform (broadcast); B loads are lane-consecutive float4 (conflict-free).
// Weight k-panels (8x512) staged to smem via cp.async double buffer.
__device__ __forceinline__ void gemm512(
    const float* __restrict__ Wb,
    const float* __restrict__ sIn, float* __restrict__ sW, float* __restrict__ sOut)
{
    const int tid = threadIdx.x;
    const int rg = tid >> 6;
    const int cg = tid & 63;
    const int rowBase = rg * 6;
    const int c0 = cg * 4;

    unsigned long long acc[6][4];
#pragma unroll
    for (int j = 0; j < 6; ++j)
#pragma unroll
        for (int m = 0; m < 4; ++m) acc[j][m] = 0ull;

    const int skk  = tid >> 6;
    const int scol = (tid & 63) * 8;

    cp_async16(sW + skk*512 + scol,     Wb + skk*512 + scol);
    cp_async16(sW + skk*512 + scol + 4, Wb + skk*512 + scol + 4);
    cp_commit();

#pragma unroll 1
    for (int p = 0; p < 64; ++p) {
        float* cb = sW + (p & 1) * 4096;
        if (p + 1 < 64) {
            float* nb = sW + ((p + 1) & 1) * 4096;
            const float* src = Wb + (p + 1) * 4096;
            cp_async16(nb + skk*512 + scol,     src + skk*512 + scol);
            cp_async16(nb + skk*512 + scol + 4, src + skk*512 + scol + 4);
            cp_commit();
            cp_wait1();
        } else {
            cp_wait0();
        }
        __syncthreads();
#pragma unroll
        for (int kk = 0; kk < 8; kk += 4) {
            const int kg = (p << 3) + kk;
            float4 a[6];
#pragma unroll
            for (int j = 0; j < 6; ++j)
                a[j] = *(const float4*)&sIn[(rowBase + j)*512 + kg];
#pragma unroll
            for (int kq = 0; kq < 4; ++kq) {
                ulonglong2 bA = *(const ulonglong2*)&cb[(kk + kq)*512 + c0];
                ulonglong2 bB = *(const ulonglong2*)&cb[(kk + kq)*512 + c0 + 256];
#pragma unroll
                for (int j = 0; j < 6; ++j) {
                    float av = (kq == 0) ? a[j].x : (kq == 1) ? a[j].y
                             : (kq == 2) ? a[j].z : a[j].w;
                    unsigned long long a2 = splat2(av);
                    ffma2(acc[j][0], a2, bA.x);
                    ffma2(acc[j][1], a2, bA.y);
                    ffma2(acc[j][2], a2, bB.x);
                    ffma2(acc[j][3], a2, bB.y);
                }
            }
        }
        __syncthreads();
    }
#pragma unroll
    for (int j = 0; j < 6; ++j) {
        *(ulonglong2*)&sOut[(rowBase + j)*512 + c0]       = make_ulonglong2(acc[j][0], acc[j][1]);
        *(ulonglong2*)&sOut[(rowBase + j)*512 + c0 + 256] = make_ulonglong2(acc[j][2], acc[j][3]);
    }
}

// Fused bias(te/pos) + LayerNorm + softplus, with JVP for two tangents.
// One warp per token (16 warps). In-place on buf.
__device__ __forceinline__ void elementwise_ln(
    float* __restrict__ buf,
    const float* __restrict__ bvec, const float* __restrict__ gvec,
    const float* __restrict__ bevec, const float* __restrict__ Wfull,
    float tval, int tok0)
{
    const int i = threadIdx.x >> 5;
    const int l = threadIdx.x & 31;
    const float pos = (float)(((tok0 + i) & 63) + 1) * (1.f/64.f);
    float* xr  = buf + i*512;
    float* u0r = buf + (16+i)*512;
    float* u1r = buf + (32+i)*512;

    float s1=0.f,s2=0.f,s3=0.f,s4=0.f,s5=0.f,s6=0.f;
    for (int k = l; k < 512; k += 32) {
        float cv = bvec[k] + tval*Wfull[k] + pos*Wfull[512+k];
        float x = xr[k] + cv;
        xr[k] = x;
        float u0 = u0r[k], u1 = u1r[k];
        s1 += x;     s2 += x*x;
        s3 += u0;    s4 += x*u0;
        s5 += u1;    s6 += x*u1;
    }
#pragma unroll
    for (int o = 16; o > 0; o >>= 1) {
        s1 += __shfl_xor_sync(0xffffffffu, s1, o);
        s2 += __shfl_xor_sync(0xffffffffu, s2, o);
        s3 += __shfl_xor_sync(0xffffffffu, s3, o);
        s4 += __shfl_xor_sync(0xffffffffu, s4, o);
        s5 += __shfl_xor_sync(0xffffffffu, s5, o);
        s6 += __shfl_xor_sync(0xffffffffu, s6, o);
    }
    const float inv = 1.f/512.f;
    float mu   = s1*inv;
    float var  = s2*inv - mu*mu;
    float r    = rsqrtf(var + EPS);
    float mu0  = s3*inv, mu1 = s5*inv;
    float cov0 = s4*inv - mu*mu0;
    float cov1 = s6*inv - mu*mu1;
    float r3c0 = r*r*r*cov0;
    float r3c1 = r*r*r*cov1;
    for (int k = l; k < 512; k += 32) {
        float x  = xr[k];
        float xc = x - mu;
        float gg = gvec[k];
        float y  = fmaf(xc*r, gg, bevec[k]);
        float e  = __expf(-fabsf(y));
        float sp = fmaxf(y, 0.f) + log1pf(e);
        float sg = (y >= 0.f) ? (1.f/(1.f+e)) : (e/(1.f+e));
        float du0 = sg * gg * (r*(u0r[k]-mu0) - xc*r3c0);
        float du1 = sg * gg * (r*(u1r[k]-mu1) - xc*r3c1);
        xr[k]  = sp;
        u0r[k] = du0;
        u1r[k] = du1;
    }
}

// Pre-kernel: g_condW[b][n] = sum_c cond[b][c] * W0[(4+c)*512+n].
// 256 CTAs x 512 thr, 8 batches per CTA; W0 column read once per CTA (L2-hot).
__global__ void __launch_bounds__(512) condw_kernel(
    const float* __restrict__ cond, const float* __restrict__ W0)
{
    __shared__ float sc[8 * 128];
    const int n  = threadIdx.x;
    const int bb = blockIdx.x * 8;
    for (int idx = n; idx < 8*128; idx += 512) sc[idx] = cond[bb*128 + idx];
    __syncthreads();
    float acc[8];
#pragma unroll
    for (int j = 0; j < 8; ++j) acc[j] = 0.f;
    for (int c = 0; c < 128; ++c) {
        float w = W0[(4 + c)*512 + n];
#pragma unroll
        for (int j = 0; j < 8; ++j) acc[j] = fmaf(sc[j*128 + c], w, acc[j]);
    }
#pragma unroll
    for (int j = 0; j < 8; ++j) g_condW[(bb + j)*512 + n] = acc[j];
}

__global__ void __launch_bounds__(512, 1) ode_kernel(
    const float* __restrict__ tptr, const float* __restrict__ z,
    const float* __restrict__ cond,
    const float* __restrict__ W0, const float* __restrict__ b0,
    const float* __restrict__ g0, const float* __restrict__ be0,
    const float* __restrict__ W1, const float* __restrict__ b1,
    const float* __restrict__ g1, const float* __restrict__ be1,
    const float* __restrict__ W2, const float* __restrict__ b2,
    const float* __restrict__ g2, const float* __restrict__ be2,
    const float* __restrict__ W3, const float* __restrict__ b3,
    float* __restrict__ out)
{
    extern __shared__ float smem[];
    float* sA = smem;            // 48x512
    float* sB = smem + 24576;    // 48x512
    float* sW = smem + 49152;    // 2 x (8x512) weight panels
    const int tid  = threadIdx.x;
    const int tok0 = blockIdx.x * 16;
    const float tval = tptr[0];

    // ---- Layer 0 (algebraic): primal = z0*W0r2 + z1*W0r3 + condW; u0=W0r2, u1=W0r3
    if (tid < 32) sW[tid] = z[tok0*2 + tid];
    __syncthreads();
    {
        const int n = tid;
        float w2  = W0[1024 + n];
        float w3  = W0[1536 + n];
        float cwv = g_condW[(tok0 >> 6)*512 + n];
#pragma unroll
        for (int i = 0; i < 16; ++i) {
            float z0 = sW[i*2], z1 = sW[i*2 + 1];
            sB[i*512 + n]        = fmaf(z0, w2, fmaf(z1, w3, cwv));
            sB[(16 + i)*512 + n] = w2;
            sB[(32 + i)*512 + n] = w3;
        }
    }
    __syncthreads();
    elementwise_ln(sB, b0, g0, be0, W0, tval, tok0);
    __syncthreads();

    // ---- Layer 1
    gemm512(W1 + 1024, sB, sW, sA);
    __syncthreads();
    elementwise_ln(sA, b1, g1, be1, W1, tval, tok0);
    __syncthreads();

    // ---- Layer 2
    gemm512(W2 + 1024, sA, sW, sB);
    __syncthreads();
    elementwise_ln(sB, b2, g2, be2, W2, tval, tok0);
    __syncthreads();

    // ---- Layer 3: per-token dots (warp per token)
    {
        const int i = tid >> 5, l = tid & 31;
        const int token = tok0 + i;
        const float pos = (float)((token & 63) + 1) * (1.f/64.f);
        const float* xr  = sB + i*512;
        const float* u0r = sB + (16+i)*512;
        const float* u1r = sB + (32+i)*512;
        float a0=0.f, a1=0.f, d0=0.f, d1=0.f;
        for (int k = l; k < 512; k += 32) {
            float2 wv = *(const float2*)&W3[(2+k)*2];
            float h = xr[k];
            a0 = fmaf(h, wv.x, a0);
            a1 = fmaf(h, wv.y, a1);
            d0 = fmaf(u0r[k], wv.x, d0);
            d1 = fmaf(u1r[k], wv.y, d1);
        }
#pragma unroll
        for (int o = 16; o > 0; o >>= 1) {
            a0 += __shfl_xor_sync(0xffffffffu, a0, o);
            a1 += __shfl_xor_sync(0xffffffffu, a1, o);
            d0 += __shfl_xor_sync(0xffffffffu, d0, o);
            d1 += __shfl_xor_sync(0xffffffffu, d1, o);
        }
        if (l == 0) {
            out[token*2 + 0] = a0 + b3[0] + tval*W3[0] + pos*W3[2];
            out[token*2 + 1] = a1 + b3[1] + tval*W3[1] + pos*W3[3];
            out[2*NTOK + token] = -(d0 + d1);
        }
    }
}

extern "C" void kernel_launch(void* const* d_in, const int* in_sizes, int n_in,
                              void* d_out, int out_size)
{
    const float* t    = (const float*)d_in[0];
    const float* z    = (const float*)d_in[1];
    const float* cond = (const float*)d_in[2];
    const float* W0   = (const float*)d_in[3];
    const float* b0   = (const float*)d_in[4];
    const float* g0   = (const float*)d_in[5];
    const float* be0  = (const float*)d_in[6];
    const float* W1   = (const float*)d_in[7];
    const float* b1   = (const float*)d_in[8];
    const float* g1   = (const float*)d_in[9];
    const float* be1  = (const float*)d_in[10];
    const float* W2   = (const float*)d_in[11];
    const float* b2   = (const float*)d_in[12];
    const float* g2   = (const float*)d_in[13];
    const float* be2  = (const float*)d_in[14];
    const float* W3   = (const float*)d_in[15];
    const float* b3   = (const float*)d_in[16];
    float* out = (float*)d_out;

    condw_kernel<<<256, 512>>>(cond, W0);

    const size_t smem_bytes = 57344 * sizeof(float);  // 229376 B
    cudaFuncSetAttribute(ode_kernel, cudaFuncAttributeMaxDynamicSharedMemorySize,
                         (int)smem_bytes);
    ode_kernel<<<NTOK/16, 512, smem_bytes>>>(
        t, z, cond, W0, b0, g0, be0, W1, b1, g1, be1,
        W2, b2, g2, be2, W3, b3, out);
}